// round 1
// baseline (speedup 1.0000x reference)
#include <cuda_runtime.h>
#include <math.h>

// Problem constants
#define BATCH 32
#define IMGH  64
#define IMGW  64
#define CIN   65          // 1 time + 64 spatial
#define NOUT  255         // linear outputs (z)
#define NPAD  256         // padded N (col 255 zero)
#define KSP   576         // spatial K = 9 taps * 64 ch
#define NCHUNK 18         // 576 / 32
#define BK    32

// Transposed weights: rows 0..575 = W[o][1+k] (spatial), row 576 = W[o][0] (time col).
// Column 255 zero-padded.
__device__ float g_Wt[(KSP + 1) * NPAD];

__global__ void transpose_W_kernel(const float* __restrict__ W) {
    int k = blockIdx.x;      // 0..576
    int o = threadIdx.x;     // 0..255
    float v = 0.0f;
    if (o < NOUT) {
        int src_col = (k < KSP) ? (k + 1) : 0;
        v = W[o * 577 + src_col];
    }
    g_Wt[k * NPAD + o] = v;
}

// Shared memory layout (floats):
//   [0, 8192)            sw   : W chunk, [32][256]
//   [8192, 24576)        region:
//       mainloop: sxp [3][64][67] (12864) at 8192 ; st [3][66] (198) at 21056
//       epilogue: outbuf [64][256] (16384) at 8192
#define SW_OFF    0
#define SXP_OFF   8192
#define ST_OFF    (8192 + 3 * 64 * 67)
#define OUTB_OFF  8192
#define SMEM_FLOATS (8192 + 64 * 256)
#define SMEM_BYTES  (SMEM_FLOATS * 4)

__global__ void __launch_bounds__(256, 2)
hypconv_kernel(const float* __restrict__ x,
               const float* __restrict__ bias,
               float* __restrict__ out) {
    extern __shared__ float smem[];
    float* sw  = smem + SW_OFF;
    float* sxp = smem + SXP_OFF;   // [3][64][67]  ch-major, padded cols 0..65 = x cols -1..64
    float* st  = smem + ST_OFF;    // [3][66]      time channel, padded cols

    const int tid = threadIdx.x;
    const int tx  = tid & 15;       // output group
    const int ty  = tid >> 4;       // pixel group
    const int p0  = ty * 4;         // first pixel of this thread

    const int bh   = blockIdx.x;    // b*64 + y
    const int bimg = bh >> 6;
    const int y    = bh & 63;

    // ---- Stage 3 clamped image rows into shared (spatial channels transposed) ----
    for (int r = 0; r < 3; r++) {
        int yy = y + r - 1;
        yy = yy < 0 ? 0 : (yy > 63 ? 63 : yy);
        const float* xrow = x + ((size_t)(bimg * IMGH + yy) * IMGW) * CIN;
        // spatial: 66 padded cols * 64 ch
        for (int idx = tid; idx < 66 * 64; idx += 256) {
            int ch   = idx & 63;
            int colp = idx >> 6;            // 0..65 -> x col colp-1 clamped
            int xc   = colp - 1;
            xc = xc < 0 ? 0 : (xc > 63 ? 63 : xc);
            sxp[r * 64 * 67 + ch * 67 + colp] = xrow[xc * CIN + 1 + ch];
        }
        // time channel
        for (int colp = tid; colp < 66; colp += 256) {
            int xc = colp - 1;
            xc = xc < 0 ? 0 : (xc > 63 ? 63 : xc);
            st[r * 66 + colp] = xrow[xc * CIN];
        }
    }

    // ---- Main GEMM: acc[p][q], q = j*4+i, output o = 4*(tx+16j)+i ----
    float acc[4][16];
#pragma unroll
    for (int p = 0; p < 4; p++)
#pragma unroll
        for (int q = 0; q < 16; q++) acc[p][q] = 0.0f;

    for (int ck = 0; ck < NCHUNK; ck++) {
        __syncthreads();
        // load W chunk (32 x 256 floats) as float4
        {
            const float4* src = (const float4*)(g_Wt + (size_t)ck * BK * NPAD);
            float4* dst = (float4*)sw;
#pragma unroll
            for (int t = 0; t < 8; t++) dst[tid + t * 256] = src[tid + t * 256];
        }
        __syncthreads();

        const int tap   = ck >> 1;       // 0..8
        const int dyr   = tap / 3;       // row 0..2
        const int dxo   = tap % 3;       // padded-col shift 0..2
        const float* arow = sxp + dyr * 64 * 67;
        const int px0 = p0 + dxo;
        const int cb  = (ck & 1) * 32;

#pragma unroll 8
        for (int k = 0; k < BK; k++) {
            const float* ar = arow + (cb + k) * 67 + px0;
            float a0 = ar[0], a1 = ar[1], a2 = ar[2], a3 = ar[3];
            const float4* swk = (const float4*)(sw + k * NPAD);
            float4 b0 = swk[tx];
            float4 b1 = swk[tx + 16];
            float4 b2 = swk[tx + 32];
            float4 b3 = swk[tx + 48];
            float bv[16] = {b0.x, b0.y, b0.z, b0.w,  b1.x, b1.y, b1.z, b1.w,
                            b2.x, b2.y, b2.z, b2.w,  b3.x, b3.y, b3.z, b3.w};
            float av[4] = {a0, a1, a2, a3};
#pragma unroll
            for (int p = 0; p < 4; p++)
#pragma unroll
                for (int q = 0; q < 16; q++)
                    acc[p][q] = fmaf(av[p], bv[q], acc[p][q]);
        }
    }

    // ---- Epilogue ----
    // t_cat per pixel: sqrt( sum over 9 taps t^2 - 8 )
    float tc[4];
#pragma unroll
    for (int p = 0; p < 4; p++) {
        float s = 0.0f;
#pragma unroll
        for (int r = 0; r < 3; r++) {
#pragma unroll
            for (int d = 0; d < 3; d++) {
                float tv = st[r * 66 + p0 + p + d];
                s = fmaf(tv, tv, s);
            }
        }
        tc[p] = sqrtf(s - 8.0f);
    }

    // time weights (row 576 of g_Wt, col 255 = 0) and bias
    float wt[16];
    float bb[16];
#pragma unroll
    for (int j = 0; j < 4; j++) {
        float4 w4 = ((const float4*)(g_Wt + (size_t)KSP * NPAD))[tx + 16 * j];
        wt[j * 4 + 0] = w4.x; wt[j * 4 + 1] = w4.y;
        wt[j * 4 + 2] = w4.z; wt[j * 4 + 3] = w4.w;
#pragma unroll
        for (int i = 0; i < 4; i++) {
            int o = 4 * (tx + 16 * j) + i;
            bb[j * 4 + i] = (o < NOUT) ? bias[o] : 0.0f;
        }
    }

    float ss[4] = {0.0f, 0.0f, 0.0f, 0.0f};
#pragma unroll
    for (int p = 0; p < 4; p++) {
#pragma unroll
        for (int q = 0; q < 16; q++) {
            float z = acc[p][q] + tc[p] * wt[q] + bb[q];
            acc[p][q] = z;
            int o = 4 * (tx + 16 * (q >> 2)) + (q & 3);
            if (o < NOUT) ss[p] = fmaf(z, z, ss[p]);
        }
    }
    // reduce sum-of-squares across the 16 output lanes (width-16 groups)
#pragma unroll
    for (int m = 8; m >= 1; m >>= 1) {
#pragma unroll
        for (int p = 0; p < 4; p++)
            ss[p] += __shfl_xor_sync(0xffffffffu, ss[p], m, 16);
    }
    float tout[4];
#pragma unroll
    for (int p = 0; p < 4; p++) tout[p] = sqrtf(1.0f + ss[p]);

    __syncthreads();   // done reading st/sxp; safe to overwrite with outbuf
    float* outbuf = smem + OUTB_OFF;    // [64][256]
#pragma unroll
    for (int p = 0; p < 4; p++) {
        float* row = outbuf + (p0 + p) * NPAD;
        if (tx == 0) row[0] = tout[p];
#pragma unroll
        for (int q = 0; q < 16; q++) {
            int o = 4 * (tx + 16 * (q >> 2)) + (q & 3);
            if (o < NOUT) row[1 + o] = acc[p][q];
        }
    }
    __syncthreads();

    // coalesced store: 64 pixels * 256 ch
    float4* og = (float4*)(out + (size_t)bh * 64 * NPAD);
    const float4* ob = (const float4*)outbuf;
#pragma unroll
    for (int t = 0; t < 16; t++) og[tid + t * 256] = ob[tid + t * 256];
}

extern "C" void kernel_launch(void* const* d_in, const int* in_sizes, int n_in,
                              void* d_out, int out_size) {
    const float* x = (const float*)d_in[0];   // (32,64,64,65)
    const float* W = (const float*)d_in[1];   // (255,577)
    const float* b = (const float*)d_in[2];   // (255)
    float* out = (float*)d_out;               // (32,64,64,256)

    transpose_W_kernel<<<KSP + 1, 256>>>(W);

    cudaFuncSetAttribute(hypconv_kernel,
                         cudaFuncAttributeMaxDynamicSharedMemorySize, SMEM_BYTES);
    hypconv_kernel<<<BATCH * IMGH, 256, SMEM_BYTES>>>(x, b, out);
}

// round 4
// speedup vs baseline: 2.0670x; 2.0670x over previous
#include <cuda_runtime.h>
#include <cuda_bf16.h>
#include <cstdint>
#include <math.h>

#define NOUT 255
#define NCHUNK 9

// ------------- prepped weights (device globals) -------------
// Per chunk c: B tile 64(k) x 256(n) bf16, stored pre-swizzled:
//   byte(k,n) = k*512 + (((n>>3) ^ (k&7))<<4) + ((n*2)&15)
__device__ __nv_bfloat16 g_Bh[NCHUNK * 64 * 256];
__device__ __nv_bfloat16 g_Bl[NCHUNK * 64 * 256];
__device__ float g_wt[256];

__global__ void prep_W(const float* __restrict__ W) {
    int c = blockIdx.x;   // chunk/tap
    int k = blockIdx.y;   // 0..63
    int n = threadIdx.x;  // 0..255
    float v = 0.0f;
    if (n < NOUT) v = W[n * 577 + 1 + c * 64 + k];
    __nv_bfloat16 h = __float2bfloat16(v);
    __nv_bfloat16 l = __float2bfloat16(v - __bfloat162float(h));
    uint32_t byte = (uint32_t)k * 512 + ((((uint32_t)n >> 3) ^ (k & 7)) << 4) + ((n * 2) & 15);
    g_Bh[(size_t)c * 16384 + byte / 2] = h;
    g_Bl[(size_t)c * 16384 + byte / 2] = l;
}
__global__ void prep_wt(const float* __restrict__ W) {
    int o = threadIdx.x;
    g_wt[o] = (o < NOUT) ? W[o * 577] : 0.0f;
}

// ------------- smem layout -------------
#define STAGE_SZ 98304
#define OFF_AH 0
#define OFF_AL 16384
#define OFF_BH 32768
#define OFF_BL 65536
#define OFF_STC  196608
#define OFF_WT   197120
#define OFF_BIAS 198144
#define OFF_SSP  199168
#define SMEM_BYTES 201216

// ------------- PTX helpers -------------
__device__ __forceinline__ uint32_t smem_u32(const void* p) {
    uint32_t a;
    asm("{ .reg .u64 t; cvta.to.shared.u64 t, %1; cvt.u32.u64 %0, t; }" : "=r"(a) : "l"(p));
    return a;
}
__device__ __forceinline__ void cp16(uint32_t dst, const void* src) {
    asm volatile("cp.async.cg.shared.global [%0], [%1], 16;" :: "r"(dst), "l"(src));
}
__device__ __forceinline__ void cp_commit() { asm volatile("cp.async.commit_group;"); }
__device__ __forceinline__ void cp_wait_all() { asm volatile("cp.async.wait_group 0;"); }

__device__ __forceinline__ void ldsm4(uint32_t* r, uint32_t a) {
    asm volatile("ldmatrix.sync.aligned.m8n8.x4.shared.b16 {%0,%1,%2,%3}, [%4];"
                 : "=r"(r[0]), "=r"(r[1]), "=r"(r[2]), "=r"(r[3]) : "r"(a));
}
__device__ __forceinline__ void ldsm4t(uint32_t* r, uint32_t a) {
    asm volatile("ldmatrix.sync.aligned.m8n8.x4.trans.shared.b16 {%0,%1,%2,%3}, [%4];"
                 : "=r"(r[0]), "=r"(r[1]), "=r"(r[2]), "=r"(r[3]) : "r"(a));
}
__device__ __forceinline__ void mma16816(float* d, const uint32_t* a, const uint32_t* b) {
    asm volatile(
        "mma.sync.aligned.m16n8k16.row.col.f32.bf16.bf16.f32 "
        "{%0,%1,%2,%3}, {%4,%5,%6,%7}, {%8,%9}, {%0,%1,%2,%3};"
        : "+f"(d[0]), "+f"(d[1]), "+f"(d[2]), "+f"(d[3])
        : "r"(a[0]), "r"(a[1]), "r"(a[2]), "r"(a[3]), "r"(b[0]), "r"(b[1]));
}

__device__ __forceinline__ int clamp64(int v) { return v < 0 ? 0 : (v > 63 ? 63 : v); }

// ------------- main kernel -------------
__global__ void __launch_bounds__(512, 1)
hyp_hmma(const float* __restrict__ x,
         const float* __restrict__ bias,
         float* __restrict__ out) {
    extern __shared__ char smem[];
    const uint32_t sb = smem_u32(smem);
    float* stc   = (float*)(smem + OFF_STC);
    float* swt   = (float*)(smem + OFF_WT);
    float* sbias = (float*)(smem + OFF_BIAS);
    float* ssp   = (float*)(smem + OFF_SSP);

    const int tid  = threadIdx.x;
    const int lane = tid & 31;
    const int warp = tid >> 5;
    const int wm = warp >> 2;          // 0..3 -> m offset 32*wm
    const int wn = warp & 3;           // 0..3 -> n offset 64*wn

    const int blk  = blockIdx.x;       // 1024
    const int bimg = blk >> 5;
    const int y0   = (blk & 31) * 2;   // 2 image rows per CTA
    const float* ximg = x + (size_t)bimg * 64 * 64 * 65;

    // aux: time weights, bias, t_cat
    if (tid < 256) {
        swt[tid]   = g_wt[tid];
        sbias[tid] = (tid < NOUT) ? bias[tid] : 0.0f;
    }
    if (tid < 128) {
        int iy = tid >> 6, ix = tid & 63;
        float s = 0.0f;
#pragma unroll
        for (int dy = -1; dy <= 1; dy++)
#pragma unroll
            for (int dx = -1; dx <= 1; dx++) {
                int yy = clamp64(y0 + iy + dy);
                int xx = clamp64(ix + dx);
                float t = __ldg(ximg + ((size_t)yy * 64 + xx) * 65);
                s = fmaf(t, t, s);
            }
        stc[tid] = sqrtf(s - 8.0f);
    }

    // ---- A conversion into stage s for tap c ----
    auto convertA = [&](int c, int s) {
        const int dy = c / 3 - 1, dx = c % 3 - 1;
        const int pl = tid >> 2;            // pixel 0..127
        const int c0 = (tid & 3) * 16;      // channel group
        const int iy = pl >> 6, ix = pl & 63;
        const int yy = clamp64(y0 + iy + dy);
        const int xx = clamp64(ix + dx);
        const float* src = ximg + ((size_t)yy * 64 + xx) * 65 + 1 + c0;
        char* aH = smem + s * STAGE_SZ + OFF_AH;
        char* aL = smem + s * STAGE_SZ + OFF_AL;
#pragma unroll
        for (int u = 0; u < 8; u++) {
            float v0 = __ldg(src + 2 * u);
            float v1 = __ldg(src + 2 * u + 1);
            __nv_bfloat16 h0 = __float2bfloat16(v0);
            __nv_bfloat16 h1 = __float2bfloat16(v1);
            __nv_bfloat16 l0 = __float2bfloat16(v0 - __bfloat162float(h0));
            __nv_bfloat16 l1 = __float2bfloat16(v1 - __bfloat162float(h1));
            uint32_t hp = ((uint32_t)__bfloat16_as_ushort(h1) << 16) | __bfloat16_as_ushort(h0);
            uint32_t lp = ((uint32_t)__bfloat16_as_ushort(l1) << 16) | __bfloat16_as_ushort(l0);
            int ch2 = (c0 + 2 * u) * 2;     // byte offset along k within 128B row
            uint32_t byte = (uint32_t)pl * 128 + ((((uint32_t)(ch2 >> 4)) ^ (pl & 7)) << 4) + (ch2 & 15);
            *(uint32_t*)(aH + byte) = hp;
            *(uint32_t*)(aL + byte) = lp;
        }
    };

    // ---- B cp.async into stage s for tap c ----
    auto loadB = [&](int c, int s) {
        const char* srcH = (const char*)g_Bh + (size_t)c * 32768;
        const char* srcL = (const char*)g_Bl + (size_t)c * 32768;
        uint32_t dstH = sb + s * STAGE_SZ + OFF_BH;
        uint32_t dstL = sb + s * STAGE_SZ + OFF_BL;
#pragma unroll
        for (int r = 0; r < 4; r++) {
            int u = tid + r * 512;
            cp16(dstH + u * 16, srcH + u * 16);
            cp16(dstL + u * 16, srcL + u * 16);
        }
    };

    float acc[2][8][4];
#pragma unroll
    for (int i = 0; i < 2; i++)
#pragma unroll
        for (int j = 0; j < 8; j++)
#pragma unroll
            for (int r = 0; r < 4; r++) acc[i][j][r] = 0.0f;

    // prologue: stage 0
    loadB(0, 0);
    cp_commit();
    convertA(0, 0);

    for (int c = 0; c < NCHUNK; c++) {
        cp_wait_all();
        __syncthreads();
        int s = c & 1;
        if (c + 1 < NCHUNK) {
            loadB(c + 1, s ^ 1);
            cp_commit();
            convertA(c + 1, s ^ 1);
        }

        const uint32_t baseA = sb + s * STAGE_SZ;
        // lane-derived ldmatrix coordinates
        const int selm = (lane >> 3) & 1;
        const int selk = lane >> 4;
        const int lr   = lane & 7;

#pragma unroll
        for (int ks = 0; ks < 4; ks++) {
            const int k0 = ks * 16;
            uint32_t ah[2][4], al[2][4];
#pragma unroll
            for (int i = 0; i < 2; i++) {
                int m  = wm * 32 + i * 16 + selm * 8 + lr;
                int kk = k0 + selk * 8;
                uint32_t byte = (uint32_t)m * 128 + ((((uint32_t)(kk >> 3)) ^ (m & 7)) << 4);
                ldsm4(ah[i], baseA + OFF_AH + byte);
                ldsm4(al[i], baseA + OFF_AL + byte);
            }
#pragma unroll
            for (int h = 0; h < 2; h++) {
                uint32_t bh[4][2], bl[4][2];
#pragma unroll
                for (int pr = 0; pr < 2; pr++) {
                    int n0 = wn * 64 + h * 32 + pr * 16;
                    int kb = k0 + selm * 8 + lr;
                    int nn = n0 + selk * 8;
                    uint32_t byte = (uint32_t)kb * 512 + ((((uint32_t)(nn >> 3)) ^ (kb & 7)) << 4);
                    uint32_t r4[4];
                    ldsm4t(r4, baseA + OFF_BH + byte);
                    bh[pr * 2][0] = r4[0]; bh[pr * 2][1] = r4[1];
                    bh[pr * 2 + 1][0] = r4[2]; bh[pr * 2 + 1][1] = r4[3];
                    ldsm4t(r4, baseA + OFF_BL + byte);
                    bl[pr * 2][0] = r4[0]; bl[pr * 2][1] = r4[1];
                    bl[pr * 2 + 1][0] = r4[2]; bl[pr * 2 + 1][1] = r4[3];
                }
#pragma unroll
                for (int i = 0; i < 2; i++)
#pragma unroll
                    for (int j = 0; j < 4; j++) {
                        mma16816(acc[i][h * 4 + j], ah[i], bh[j]);
                        mma16816(acc[i][h * 4 + j], ah[i], bl[j]);
                        mma16816(acc[i][h * 4 + j], al[i], bh[j]);
                    }
            }
        }
    }

    __syncthreads();   // everyone done reading stage smem

    // ---------------- epilogue ----------------
    float* zbuf = (float*)smem;     // [128][260], col0 = t_out, cols 1..255 = z
    const int q  = lane >> 2;
    const int c2 = (lane & 3) * 2;

#pragma unroll
    for (int i = 0; i < 2; i++) {
#pragma unroll
        for (int rr = 0; rr < 2; rr++) {
            int p = wm * 32 + i * 16 + rr * 8 + q;
            float tc = stc[p];
            float ssq = 0.0f;
            float* zrow = zbuf + (size_t)p * 260 + 1;
#pragma unroll
            for (int j = 0; j < 8; j++) {
                int o0 = wn * 64 + j * 8 + c2;
                float z0 = acc[i][j][rr * 2 + 0] + tc * swt[o0] + sbias[o0];
                float z1 = acc[i][j][rr * 2 + 1] + tc * swt[o0 + 1] + sbias[o0 + 1];
                ssq = fmaf(z0, z0, fmaf(z1, z1, ssq));
                zrow[o0] = z0;
                zrow[o0 + 1] = z1;
            }
            ssq += __shfl_xor_sync(0xffffffffu, ssq, 1);
            ssq += __shfl_xor_sync(0xffffffffu, ssq, 2);
            if ((lane & 3) == 0) ssp[p * 4 + wn] = ssq;
        }
    }
    __syncthreads();
    if (tid < 128) {
        float ssum = ssp[tid * 4] + ssp[tid * 4 + 1] + ssp[tid * 4 + 2] + ssp[tid * 4 + 3];
        zbuf[(size_t)tid * 260] = sqrtf(1.0f + ssum);
    }
    __syncthreads();

    // coalesced copy out: 128 rows x 256 floats
    float4* og = (float4*)(out + (size_t)blk * 128 * 256);
#pragma unroll
    for (int u = 0; u < 16; u++) {
        int idx  = tid + u * 512;
        int row  = idx >> 6;
        int col4 = idx & 63;
        og[idx] = *(float4*)(zbuf + (size_t)row * 260 + col4 * 4);
    }
}

// ------------- launch -------------
extern "C" void kernel_launch(void* const* d_in, const int* in_sizes, int n_in,
                              void* d_out, int out_size) {
    const float* x = (const float*)d_in[0];   // (32,64,64,65)
    const float* W = (const float*)d_in[1];   // (255,577)
    const float* b = (const float*)d_in[2];   // (255)
    float* out = (float*)d_out;               // (32,64,64,256)

    prep_W<<<dim3(NCHUNK, 64), 256>>>(W);
    prep_wt<<<1, 256>>>(W);

    cudaFuncSetAttribute(hyp_hmma, cudaFuncAttributeMaxDynamicSharedMemorySize, SMEM_BYTES);
    hyp_hmma<<<1024, 512, SMEM_BYTES>>>(x, b, out);
}

// round 8
// speedup vs baseline: 4.7591x; 2.3024x over previous
#include <cuda_runtime.h>
#include <cuda_fp16.h>
#include <cstdint>
#include <math.h>

#define NOUT 255
#define NCHUNK 9

// ------------- prepped weights (device globals) -------------
// Per chunk c: B tile 64(k) x 256(n) fp16, stored pre-swizzled:
//   byte(k,n) = k*512 + (((n>>3) ^ (k&7))<<4) + ((n*2)&15)
__device__ __half g_B[NCHUNK * 64 * 256];
__device__ float g_wt[256];

__global__ void prep_W(const float* __restrict__ W) {
    int c = blockIdx.x;   // chunk/tap
    int k = blockIdx.y;   // 0..63
    int n = threadIdx.x;  // 0..255
    float v = 0.0f;
    if (n < NOUT) v = W[n * 577 + 1 + c * 64 + k];
    uint32_t byte = (uint32_t)k * 512 + ((((uint32_t)n >> 3) ^ (k & 7)) << 4) + ((n * 2) & 15);
    g_B[(size_t)c * 16384 + byte / 2] = __float2half(v);
}
__global__ void prep_wt(const float* __restrict__ W) {
    int o = threadIdx.x;
    g_wt[o] = (o < NOUT) ? W[o * 577] : 0.0f;
}

// ------------- smem layout -------------
// stage: A 16KB + B 32KB = 48KB, double buffered = 96KB at offset 0
// epilogue zbuf [128][260] floats = 133120 B overlaps stages (dead then)
// aux (stc/wt/bias/ssp) lives after zbuf region
#define STAGE_SZ 49152
#define OFF_A 0
#define OFF_B 16384
#define OFF_STC  133120
#define OFF_WT   133632
#define OFF_BIAS 134656
#define OFF_SSP  135680
#define SMEM_BYTES 137728

// ------------- PTX helpers -------------
__device__ __forceinline__ uint32_t smem_u32(const void* p) {
    uint32_t a;
    asm("{ .reg .u64 t; cvta.to.shared.u64 t, %1; cvt.u32.u64 %0, t; }" : "=r"(a) : "l"(p));
    return a;
}
__device__ __forceinline__ void cp16(uint32_t dst, const void* src) {
    asm volatile("cp.async.cg.shared.global [%0], [%1], 16;" :: "r"(dst), "l"(src));
}
__device__ __forceinline__ void cp_commit() { asm volatile("cp.async.commit_group;"); }
__device__ __forceinline__ void cp_wait_all() { asm volatile("cp.async.wait_group 0;"); }

__device__ __forceinline__ void ldsm4(uint32_t* r, uint32_t a) {
    asm volatile("ldmatrix.sync.aligned.m8n8.x4.shared.b16 {%0,%1,%2,%3}, [%4];"
                 : "=r"(r[0]), "=r"(r[1]), "=r"(r[2]), "=r"(r[3]) : "r"(a));
}
__device__ __forceinline__ void ldsm4t(uint32_t* r, uint32_t a) {
    asm volatile("ldmatrix.sync.aligned.m8n8.x4.trans.shared.b16 {%0,%1,%2,%3}, [%4];"
                 : "=r"(r[0]), "=r"(r[1]), "=r"(r[2]), "=r"(r[3]) : "r"(a));
}
__device__ __forceinline__ void mma16816(float* d, const uint32_t* a, const uint32_t* b) {
    asm volatile(
        "mma.sync.aligned.m16n8k16.row.col.f32.f16.f16.f32 "
        "{%0,%1,%2,%3}, {%4,%5,%6,%7}, {%8,%9}, {%0,%1,%2,%3};"
        : "+f"(d[0]), "+f"(d[1]), "+f"(d[2]), "+f"(d[3])
        : "r"(a[0]), "r"(a[1]), "r"(a[2]), "r"(a[3]), "r"(b[0]), "r"(b[1]));
}

__device__ __forceinline__ int clamp64(int v) { return v < 0 ? 0 : (v > 63 ? 63 : v); }

// ------------- main kernel -------------
__global__ void __launch_bounds__(512, 1)
hyp_hmma(const float* __restrict__ x,
         const float* __restrict__ bias,
         float* __restrict__ out) {
    extern __shared__ char smem[];
    const uint32_t sb = smem_u32(smem);
    float* stc   = (float*)(smem + OFF_STC);
    float* swt   = (float*)(smem + OFF_WT);
    float* sbias = (float*)(smem + OFF_BIAS);
    float* ssp   = (float*)(smem + OFF_SSP);

    const int tid  = threadIdx.x;
    const int lane = tid & 31;
    const int warp = tid >> 5;
    const int wm = warp >> 2;          // 0..3 -> m offset 32*wm
    const int wn = warp & 3;           // 0..3 -> n offset 64*wn

    const int blk  = blockIdx.x;       // 1024
    const int bimg = blk >> 5;
    const int y0   = (blk & 31) * 2;   // 2 image rows per CTA
    const float* ximg = x + (size_t)bimg * 64 * 64 * 65;

    // aux: time weights, bias, t_cat
    if (tid < 256) {
        swt[tid]   = g_wt[tid];
        sbias[tid] = (tid < NOUT) ? bias[tid] : 0.0f;
    }
    if (tid < 128) {
        int iy = tid >> 6, ix = tid & 63;
        float s = 0.0f;
#pragma unroll
        for (int dy = -1; dy <= 1; dy++)
#pragma unroll
            for (int dx = -1; dx <= 1; dx++) {
                int yy = clamp64(y0 + iy + dy);
                int xx = clamp64(ix + dx);
                float t = __ldg(ximg + ((size_t)yy * 64 + xx) * 65);
                s = fmaf(t, t, s);
            }
        stc[tid] = sqrtf(s - 8.0f);
    }

    // ---- A conversion (fp16) into stage s for tap c ----
    auto convertA = [&](int c, int s) {
        const int dy = c / 3 - 1, dx = c % 3 - 1;
        const int pl = tid >> 2;            // pixel 0..127
        const int c0 = (tid & 3) * 16;      // 16 channels per thread
        const int iy = pl >> 6, ix = pl & 63;
        const int yy = clamp64(y0 + iy + dy);
        const int xx = clamp64(ix + dx);
        const float* src = ximg + ((size_t)yy * 64 + xx) * 65 + 1 + c0;
        char* aP = smem + s * STAGE_SZ + OFF_A;
        uint32_t w[8];
#pragma unroll
        for (int u = 0; u < 8; u++) {
            float v0 = __ldg(src + 2 * u);
            float v1 = __ldg(src + 2 * u + 1);
            __half2 hv = __floats2half2_rn(v0, v1);
            w[u] = *(uint32_t*)&hv;
        }
        // two 16B swizzle cells: k-cell index = c0/8 and c0/8+1
        const int k4 = (tid & 3) * 2;
        uint32_t b0 = (uint32_t)pl * 128 + ((((uint32_t)(k4 + 0)) ^ (pl & 7)) << 4);
        uint32_t b1 = (uint32_t)pl * 128 + ((((uint32_t)(k4 + 1)) ^ (pl & 7)) << 4);
        *(uint4*)(aP + b0) = make_uint4(w[0], w[1], w[2], w[3]);
        *(uint4*)(aP + b1) = make_uint4(w[4], w[5], w[6], w[7]);
    };

    // ---- B cp.async into stage s for tap c (32KB) ----
    auto loadB = [&](int c, int s) {
        const char* srcB = (const char*)g_B + (size_t)c * 32768;
        uint32_t dstB = sb + s * STAGE_SZ + OFF_B;
#pragma unroll
        for (int r = 0; r < 4; r++) {
            int u = tid + r * 512;
            cp16(dstB + u * 16, srcB + u * 16);
        }
    };

    float acc[2][8][4];
#pragma unroll
    for (int i = 0; i < 2; i++)
#pragma unroll
        for (int j = 0; j < 8; j++)
#pragma unroll
            for (int r = 0; r < 4; r++) acc[i][j][r] = 0.0f;

    // prologue: stage 0
    loadB(0, 0);
    cp_commit();
    convertA(0, 0);

    for (int c = 0; c < NCHUNK; c++) {
        cp_wait_all();
        __syncthreads();
        int s = c & 1;
        if (c + 1 < NCHUNK) {
            loadB(c + 1, s ^ 1);
            cp_commit();
            convertA(c + 1, s ^ 1);
        }

        const uint32_t baseA = sb + s * STAGE_SZ;
        const int selm = (lane >> 3) & 1;
        const int selk = lane >> 4;
        const int lr   = lane & 7;

#pragma unroll
        for (int ks = 0; ks < 4; ks++) {
            const int k0 = ks * 16;
            uint32_t ah[2][4];
#pragma unroll
            for (int i = 0; i < 2; i++) {
                int m  = wm * 32 + i * 16 + selm * 8 + lr;
                int kk = k0 + selk * 8;
                uint32_t byte = (uint32_t)m * 128 + ((((uint32_t)(kk >> 3)) ^ (m & 7)) << 4);
                ldsm4(ah[i], baseA + OFF_A + byte);
            }
#pragma unroll
            for (int h = 0; h < 2; h++) {
                uint32_t bh[4][2];
#pragma unroll
                for (int pr = 0; pr < 2; pr++) {
                    int n0 = wn * 64 + h * 32 + pr * 16;
                    int kb = k0 + selm * 8 + lr;
                    int nn = n0 + selk * 8;
                    uint32_t byte = (uint32_t)kb * 512 + ((((uint32_t)(nn >> 3)) ^ (kb & 7)) << 4);
                    uint32_t r4[4];
                    ldsm4t(r4, baseA + OFF_B + byte);
                    bh[pr * 2][0] = r4[0]; bh[pr * 2][1] = r4[1];
                    bh[pr * 2 + 1][0] = r4[2]; bh[pr * 2 + 1][1] = r4[3];
                }
#pragma unroll
                for (int i = 0; i < 2; i++)
#pragma unroll
                    for (int j = 0; j < 4; j++)
                        mma16816(acc[i][h * 4 + j], ah[i], bh[j]);
            }
        }
    }

    __syncthreads();   // everyone done reading stage smem

    // ---------------- epilogue ----------------
    float* zbuf = (float*)smem;     // [128][260], col0 = t_out, cols 1..255 = z
    const int q  = lane >> 2;
    const int c2 = (lane & 3) * 2;

#pragma unroll
    for (int i = 0; i < 2; i++) {
#pragma unroll
        for (int rr = 0; rr < 2; rr++) {
            int p = wm * 32 + i * 16 + rr * 8 + q;
            float tc = stc[p];
            float ssq = 0.0f;
            float* zrow = zbuf + (size_t)p * 260 + 1;
#pragma unroll
            for (int j = 0; j < 8; j++) {
                int o0 = wn * 64 + j * 8 + c2;
                float z0 = acc[i][j][rr * 2 + 0] + tc * swt[o0] + sbias[o0];
                float z1 = acc[i][j][rr * 2 + 1] + tc * swt[o0 + 1] + sbias[o0 + 1];
                ssq = fmaf(z0, z0, fmaf(z1, z1, ssq));
                zrow[o0] = z0;
                zrow[o0 + 1] = z1;
            }
            ssq += __shfl_xor_sync(0xffffffffu, ssq, 1);
            ssq += __shfl_xor_sync(0xffffffffu, ssq, 2);
            if ((lane & 3) == 0) ssp[p * 4 + wn] = ssq;
        }
    }
    __syncthreads();
    if (tid < 128) {
        float ssum = ssp[tid * 4] + ssp[tid * 4 + 1] + ssp[tid * 4 + 2] + ssp[tid * 4 + 3];
        zbuf[(size_t)tid * 260] = sqrtf(1.0f + ssum);
    }
    __syncthreads();

    // coalesced copy out: 128 rows x 256 floats
    float4* og = (float4*)(out + (size_t)blk * 128 * 256);
#pragma unroll
    for (int u = 0; u < 16; u++) {
        int idx  = tid + u * 512;
        int row  = idx >> 6;
        int col4 = idx & 63;
        og[idx] = *(float4*)(zbuf + (size_t)row * 260 + col4 * 4);
    }
}

// ------------- launch -------------
extern "C" void kernel_launch(void* const* d_in, const int* in_sizes, int n_in,
                              void* d_out, int out_size) {
    const float* x = (const float*)d_in[0];   // (32,64,64,65)
    const float* W = (const float*)d_in[1];   // (255,577)
    const float* b = (const float*)d_in[2];   // (255)
    float* out = (float*)d_out;               // (32,64,64,256)

    prep_W<<<dim3(NCHUNK, 64), 256>>>(W);
    prep_wt<<<1, 256>>>(W);

    cudaFuncSetAttribute(hyp_hmma, cudaFuncAttributeMaxDynamicSharedMemorySize, SMEM_BYTES);
    hyp_hmma<<<1024, 512, SMEM_BYTES>>>(x, b, out);
}